// round 1
// baseline (speedup 1.0000x reference)
#include <cuda_runtime.h>
#include <math.h>

#define Bsz   32
#define Ssz   20
#define Psz   256
#define HIDN  128
#define MIDN  64
#define G2N   16
#define OBSN  8
#define PREDN 12
#define OUTN  5
#define RROWS (Psz*Bsz)          // 8192 rows, r = p*32 + b  (p-major)
#define ZC    (MIDN+HIDN)        // 192
#define XP_ELEMS (Bsz*PREDN*Psz*3)   // 294912

// ---------------- device scratch (static globals: allowed) ----------------
__device__ float g_c[RROWS*HIDN];          // carry (cell state), 4 MB
__device__ float g_H[(size_t)RROWS*G2N*HIDN]; // pooled H, 64 MB
__device__ float g_z[RROWS*ZC];            // [e | a], 6 MB
__device__ float g_h[RROWS*HIDN];          // hidden h, 4 MB
__device__ float g_o[RROWS*OUTN];          // last output
__device__ unsigned char g_list[Psz*Psz];  // per-p neighbor ids grouped by cell
__device__ int g_off[Psz*(G2N+1)];         // per-p per-cell offsets
__device__ unsigned int g_active[Psz];     // per-p active-cell bitmask

__device__ __forceinline__ float sigf(float x){ return 1.f/(1.f+expf(-x)); }

// ---------------- init carry = relu(b_prev) broadcast ----------------
__global__ void k_init(const float* __restrict__ bprev){
  int i = blockIdx.x*256 + threadIdx.x;
  if (i < RROWS*HIDN){ float v = bprev[i & (HIDN-1)]; g_c[i] = v > 0.f ? v : 0.f; }
}

// ---------------- mask + bucketed neighbor lists + active bitmask ----------------
// pred=0: positions/pid from x[0, t, :, :]; pred=1: pid from x[0, S-1, :, 0], pos from g_o (b=0)
__global__ void k_mask(const float* __restrict__ x, int t, int pred){
  __shared__ float spid[Psz], spx[Psz], spy[Psz];
  __shared__ unsigned char garr[Psz];
  __shared__ int cnt[G2N], off[G2N+1];
  int p = blockIdx.x, q = threadIdx.x;
  if (pred){
    spid[q] = x[((size_t)(Ssz-1)*Psz + q)*3 + 0];
    spx[q]  = g_o[(q*Bsz + 0)*OUTN + 0];
    spy[q]  = g_o[(q*Bsz + 0)*OUTN + 1];
  } else {
    const float* xb = x + (size_t)(t*Psz)*3;
    spid[q] = xb[q*3+0]; spx[q] = xb[q*3+1]; spy[q] = xb[q*3+2];
  }
  __syncthreads();
  const float Rx = 0.2f, Ry = 0.2f, CELLF = 0.1f;
  float lx = spx[p]-Rx, rxb = spx[p]+Rx, by = spy[p]-Ry, ty = spy[p]+Ry;
  float ox = spx[q], oy = spy[q];
  bool inb   = (ox < rxb) && (ox >= lx) && (oy < ty) && (oy >= by);
  bool valid = (spid[p] != 0.f) && (spid[q] != 0.f) && (spid[p] != spid[q]);
  int cx = (int)floorf((ox - lx)/CELLF);
  int cy = (int)floorf((oy - by)/CELLF);
  int idx = cx + cy*4; idx = idx < 0 ? 0 : (idx > 15 ? 15 : idx);
  garr[q] = (inb && valid) ? (unsigned char)idx : (unsigned char)255;
  __syncthreads();
  if (q < G2N){
    int c = 0;
    for (int o = 0; o < Psz; o++) if (garr[o] == (unsigned char)q) c++;
    cnt[q] = c;
  }
  __syncthreads();
  if (q == 0){
    int s = 0; unsigned int act = 0;
    for (int g = 0; g < G2N; g++){ off[g] = s; if (cnt[g]) act |= (1u<<g); s += cnt[g]; }
    off[G2N] = s;
    g_active[p] = act;
    for (int g = 0; g <= G2N; g++) g_off[p*(G2N+1)+g] = off[g];
  }
  __syncthreads();
  if (q < G2N){
    int w = off[q];
    for (int o = 0; o < Psz; o++)
      if (garr[o] == (unsigned char)q) g_list[p*Psz + (w++)] = (unsigned char)o;
  }
}

// ---------------- H build: per (b, 16-p tile), smem-cached c[b] ----------------
#define PTILE 16
__global__ void k_hbuild(){
  extern __shared__ float cs[];                       // 256*128 floats = 128 KB
  __shared__ unsigned char ls[PTILE*Psz];             // 4 KB
  __shared__ int offs[PTILE*(G2N+1)];
  int b = blockIdx.x, pt = blockIdx.y;
  int tid = threadIdx.x;                              // 256
  int pbase = pt*PTILE;
  for (int i = tid; i < Psz*HIDN; i += 256)
    cs[i] = g_c[((size_t)(i>>7)*Bsz + b)*HIDN + (i & 127)];
  for (int i = tid; i < PTILE*Psz; i += 256)
    ls[i] = g_list[(pbase + (i>>8))*Psz + (i & 255)];
  for (int i = tid; i < PTILE*(G2N+1); i += 256)
    offs[i] = g_off[(pbase + i/(G2N+1))*(G2N+1) + i%(G2N+1)];
  __syncthreads();
  int f = tid & 127, lane = tid >> 7;
  for (int pi = 0; pi < PTILE/2; pi++){
    int pl = lane*(PTILE/2) + pi;
    int p  = pbase + pl;
    unsigned int act = g_active[p];
    float* Hrow = g_H + (size_t)(p*Bsz + b)*(G2N*HIDN);
    const unsigned char* lrow = ls + pl*Psz;
    const int* orow = offs + pl*(G2N+1);
    for (int g = 0; g < G2N; g++){
      if (!((act>>g)&1u)) continue;
      int s = orow[g], e = orow[g+1];
      float a0 = 0.f, a1 = 0.f;
      int j = s;
      for (; j+1 < e; j += 2){
        a0 += cs[((int)lrow[j])*HIDN + f];
        a1 += cs[((int)lrow[j+1])*HIDN + f];
      }
      if (j < e) a0 += cs[((int)lrow[j])*HIDN + f];
      Hrow[g*HIDN + f] = a0 + a1;
    }
  }
}

// ---------------- soc GEMM (skips inactive cells) + e, writes z = [e|a] ----------------
__global__ void k_socgemm(const float* __restrict__ x,
                          const float* __restrict__ Wsoc,
                          const float* __restrict__ bsoc,
                          const float* __restrict__ Win,
                          const float* __restrict__ bin,
                          int t, int pred){
  __shared__ float Hs[16][72];
  __shared__ float Ws[16][132];
  int mt = blockIdx.x;          // 128 tiles of 64 rows
  int r0 = mt*64;
  int p0 = r0 >> 5, p1 = p0 + 1;
  unsigned int a0m = g_active[p0], a1m = g_active[p1];
  unsigned int un = a0m | a1m;
  int tI = threadIdx.x;
  int tx = tI & 31, ty = tI >> 5;
  int n0 = tx*4, m0 = ty*8;
  float acc[8][4];
  #pragma unroll
  for (int i = 0; i < 8; i++)
    #pragma unroll
    for (int j = 0; j < 4; j++) acc[i][j] = 0.f;
  int lm = tI >> 2;           // load row 0..63
  int lk = (tI & 3)*4;        // k quad within 16
  unsigned int am_ld = (lm < 32) ? a0m : a1m;
  const float* Hbase = g_H + (size_t)(r0+lm)*(G2N*HIDN);

  for (int g = 0; g < G2N; g++){
    if (!((un>>g)&1u)) continue;
    bool hz = ((am_ld>>g)&1u) == 0u;
    for (int kc = 0; kc < 8; kc++){
      int kb = g*HIDN + kc*16;
      float4 hv = hz ? make_float4(0.f,0.f,0.f,0.f)
                     : *(const float4*)(Hbase + kb + lk);
      float4 wv[2]; int wn[2], wkq[2];
      #pragma unroll
      for (int i = 0; i < 2; i++){
        int idx = tI + i*256;
        wn[i] = idx >> 2; wkq[i] = (idx & 3)*4;
        wv[i] = *(const float4*)(Wsoc + (size_t)wn[i]*2048 + kb + wkq[i]);
      }
      __syncthreads();
      Hs[lk+0][lm]=hv.x; Hs[lk+1][lm]=hv.y; Hs[lk+2][lm]=hv.z; Hs[lk+3][lm]=hv.w;
      #pragma unroll
      for (int i = 0; i < 2; i++){
        Ws[wkq[i]+0][wn[i]]=wv[i].x; Ws[wkq[i]+1][wn[i]]=wv[i].y;
        Ws[wkq[i]+2][wn[i]]=wv[i].z; Ws[wkq[i]+3][wn[i]]=wv[i].w;
      }
      __syncthreads();
      #pragma unroll
      for (int kk = 0; kk < 16; kk++){
        float4 w  = *(const float4*)(&Ws[kk][n0]);
        float4 h0 = *(const float4*)(&Hs[kk][m0]);
        float4 h1 = *(const float4*)(&Hs[kk][m0+4]);
        float hh[8] = {h0.x,h0.y,h0.z,h0.w,h1.x,h1.y,h1.z,h1.w};
        float ww[4] = {w.x,w.y,w.z,w.w};
        #pragma unroll
        for (int i = 0; i < 8; i++)
          #pragma unroll
          for (int j = 0; j < 4; j++)
            acc[i][j] += hh[i]*ww[j];
      }
    }
  }
  // a = relu(acc + b_soc) -> z[:, 64:192]
  #pragma unroll
  for (int i = 0; i < 8; i++){
    int r = r0 + m0 + i;
    float* zrow = g_z + (size_t)r*ZC + MIDN;
    #pragma unroll
    for (int j = 0; j < 4; j++){
      float v = acc[i][j] + bsoc[n0+j];
      zrow[n0+j] = v > 0.f ? v : 0.f;
    }
  }
  // e = relu(pos @ Win^T + bin) -> z[:, 0:64]
  for (int i = tI; i < 64*MIDN; i += 256){
    int mm = i >> 6, j = i & 63;
    int r = r0 + mm;
    int b = r & 31, p = r >> 5;
    float px, py;
    if (pred){ px = g_o[r*OUTN+0]; py = g_o[r*OUTN+1]; }
    else {
      const float* xr = x + (size_t)(((b*Ssz)+t)*Psz + p)*3;
      px = xr[1]; py = xr[2];
    }
    float v = px*Win[j*2+0] + py*Win[j*2+1] + bin[j];
    g_z[(size_t)r*ZC + j] = v > 0.f ? v : 0.f;
  }
}

// ---------------- LSTM gates (i,g,o only; f is dead) -> c, h ----------------
__global__ void k_lstm(const float* __restrict__ Wih,
                       const float* __restrict__ bih,
                       const float* __restrict__ bhh){
  __shared__ float Zs[16][68];
  __shared__ float Wg3[3][16][36];
  int mt = blockIdx.x, jt = blockIdx.y;
  int r0 = mt*64, j0 = jt*32;
  int tI = threadIdx.x;
  int tx = tI & 31, ty = tI >> 5;
  int m0 = ty*8;
  float ai[8], ag[8], ao[8];
  #pragma unroll
  for (int i = 0; i < 8; i++){ ai[i]=0.f; ag[i]=0.f; ao[i]=0.f; }
  const int grow0 = 0, grow1 = 256, grow2 = 384;
  int lm = tI >> 2, lk = (tI & 3)*4;
  for (int kc = 0; kc < 12; kc++){
    int kb = kc*16;
    float4 zv = *(const float4*)(g_z + (size_t)(r0+lm)*ZC + kb + lk);
    float4 wv[2]; int wg[2], wj[2], wk[2]; bool wval[2];
    #pragma unroll
    for (int i = 0; i < 2; i++){
      int idx = tI + i*256; wval[i] = idx < 384;
      wg[i]=0; wj[i]=0; wk[i]=0;
      if (wval[i]){
        wg[i] = idx/128; int rs = idx%128; wj[i] = rs>>2; wk[i] = (rs&3)*4;
        int baser = (wg[i]==0?grow0:(wg[i]==1?grow1:grow2)) + j0 + wj[i];
        wv[i] = *(const float4*)(Wih + (size_t)baser*ZC + kb + wk[i]);
      }
    }
    __syncthreads();
    Zs[lk+0][lm]=zv.x; Zs[lk+1][lm]=zv.y; Zs[lk+2][lm]=zv.z; Zs[lk+3][lm]=zv.w;
    #pragma unroll
    for (int i = 0; i < 2; i++){
      if (wval[i]){
        Wg3[wg[i]][wk[i]+0][wj[i]]=wv[i].x; Wg3[wg[i]][wk[i]+1][wj[i]]=wv[i].y;
        Wg3[wg[i]][wk[i]+2][wj[i]]=wv[i].z; Wg3[wg[i]][wk[i]+3][wj[i]]=wv[i].w;
      }
    }
    __syncthreads();
    #pragma unroll
    for (int kk = 0; kk < 16; kk++){
      float4 z0 = *(const float4*)(&Zs[kk][m0]);
      float4 z1 = *(const float4*)(&Zs[kk][m0+4]);
      float zz[8] = {z0.x,z0.y,z0.z,z0.w,z1.x,z1.y,z1.z,z1.w};
      float wi = Wg3[0][kk][tx], wgg = Wg3[1][kk][tx], wo = Wg3[2][kk][tx];
      #pragma unroll
      for (int i = 0; i < 8; i++){
        ai[i] += zz[i]*wi; ag[i] += zz[i]*wgg; ao[i] += zz[i]*wo;
      }
    }
    __syncthreads();
  }
  int j = j0 + tx;
  float bi_ = bih[j]       + bhh[j];
  float bg_ = bih[256 + j] + bhh[256 + j];
  float bo_ = bih[384 + j] + bhh[384 + j];
  #pragma unroll
  for (int i = 0; i < 8; i++){
    int r = r0 + m0 + i;
    float ci = sigf(ai[i]+bi_)*tanhf(ag[i]+bg_);
    float hh = sigf(ao[i]+bo_)*tanhf(ci);
    g_c[(size_t)r*HIDN + j] = ci;
    g_h[(size_t)r*HIDN + j] = hh;
  }
}

// ---------------- output head o = h @ Wout^T + bout ----------------
__global__ void k_out(const float* __restrict__ Wout, const float* __restrict__ bout,
                      float* __restrict__ out, int pred, int kstep){
  int warp = threadIdx.x >> 5, lane = threadIdx.x & 31;
  int r = blockIdx.x*8 + warp;
  float hv[4];
  #pragma unroll
  for (int i = 0; i < 4; i++) hv[i] = g_h[(size_t)r*HIDN + lane + i*32];
  float res[5];
  #pragma unroll
  for (int c = 0; c < 5; c++){
    float s = 0.f;
    #pragma unroll
    for (int i = 0; i < 4; i++) s += hv[i]*__ldg(Wout + c*HIDN + lane + i*32);
    #pragma unroll
    for (int d = 16; d > 0; d >>= 1) s += __shfl_xor_sync(0xffffffffu, s, d);
    res[c] = s + bout[c];
  }
  if (lane == 0){
    int b = r & 31, p = r >> 5;
    #pragma unroll
    for (int c = 0; c < 5; c++){
      g_o[r*OUTN + c] = res[c];
      if (pred)
        out[(size_t)XP_ELEMS + ((size_t)(b*PREDN + kstep)*Psz + p)*OUTN + c] = res[c];
    }
  }
}

// ---------------- write xp[b,k,p,:] = (pid, prev o.xy) ----------------
__global__ void k_xpwrite(const float* __restrict__ x, float* __restrict__ out, int kstep){
  int i = blockIdx.x*256 + threadIdx.x;   // i == r == p*32+b
  if (i >= RROWS) return;
  int b = i & 31, p = i >> 5;
  float pid = x[((size_t)(b*Ssz + Ssz-1)*Psz + p)*3 + 0];
  size_t base = ((size_t)(b*PREDN + kstep)*Psz + p)*3;
  out[base+0] = pid;
  out[base+1] = g_o[i*OUTN + 0];
  out[base+2] = g_o[i*OUTN + 1];
}

// ---------------- launch ----------------
extern "C" void kernel_launch(void* const* d_in, const int* in_sizes, int n_in,
                              void* d_out, int out_size){
  const float* x    = (const float*)d_in[0];
  const float* Win  = (const float*)d_in[1];
  const float* bin  = (const float*)d_in[2];
  const float* Wsoc = (const float*)d_in[3];
  const float* bsoc = (const float*)d_in[4];
  const float* bprev= (const float*)d_in[5];
  const float* Wih  = (const float*)d_in[6];
  const float* bih  = (const float*)d_in[7];
  const float* bhh  = (const float*)d_in[8];
  const float* Wout = (const float*)d_in[9];
  const float* bout = (const float*)d_in[10];
  float* out = (float*)d_out;

  cudaFuncSetAttribute(k_hbuild, cudaFuncAttributeMaxDynamicSharedMemorySize, Psz*HIDN*4);

  k_init<<<(RROWS*HIDN + 255)/256, 256>>>(bprev);
  for (int t = 0; t < OBSN; t++){
    k_mask<<<Psz, Psz>>>(x, t, 0);
    k_hbuild<<<dim3(Bsz, Psz/PTILE), 256, Psz*HIDN*4>>>();
    k_socgemm<<<RROWS/64, 256>>>(x, Wsoc, bsoc, Win, bin, t, 0);
    k_lstm<<<dim3(RROWS/64, 4), 256>>>(Wih, bih, bhh);
    k_out<<<RROWS/8, 256>>>(Wout, bout, out, 0, 0);
  }
  for (int k = 0; k < PREDN; k++){
    k_xpwrite<<<RROWS/256, 256>>>(x, out, k);
    k_mask<<<Psz, Psz>>>(x, 0, 1);
    k_hbuild<<<dim3(Bsz, Psz/PTILE), 256, Psz*HIDN*4>>>();
    k_socgemm<<<RROWS/64, 256>>>(x, Wsoc, bsoc, Win, bin, 0, 1);
    k_lstm<<<dim3(RROWS/64, 4), 256>>>(Wih, bih, bhh);
    k_out<<<RROWS/8, 256>>>(Wout, bout, out, 1, k);
  }
}

// round 3
// speedup vs baseline: 1.6921x; 1.6921x over previous
#include <cuda_runtime.h>
#include <math.h>

#define Bsz   32
#define Ssz   20
#define Psz   256
#define HIDN  128
#define MIDN  64
#define G2N   16
#define OBSN  8
#define PREDN 12
#define OUTN  5
#define RROWS (Psz*Bsz)          // 8192 rows, r = p*32 + b  (p-major)
#define ZC    (MIDN+HIDN)        // 192
#define XP_ELEMS (Bsz*PREDN*Psz*3)   // 294912

// ---------------- device scratch ----------------
__device__ float g_c[RROWS*HIDN];          // carry (cell state), 4 MB
__device__ float g_z[RROWS*ZC];            // [e | a], 6 MB
__device__ float g_h[RROWS*HIDN];          // hidden h, 4 MB
__device__ float g_o[RROWS*OUTN];          // last output
__device__ unsigned char g_list[Psz*Psz];  // per-p neighbor ids grouped by cell
__device__ int g_off[Psz*(G2N+1)];         // per-p per-cell offsets
__device__ unsigned int g_active[Psz];     // per-p active-cell bitmask

__device__ __forceinline__ float sigf(float x){ return 1.f/(1.f+expf(-x)); }

// ---------------- init carry = relu(b_prev) broadcast ----------------
__global__ void k_init(const float* __restrict__ bprev){
  int i = blockIdx.x*256 + threadIdx.x;
  if (i < RROWS*HIDN){ float v = bprev[i & (HIDN-1)]; g_c[i] = v > 0.f ? v : 0.f; }
}

// ---------------- mask + bucketed neighbor lists + active bitmask ----------------
__global__ void k_mask(const float* __restrict__ x, int t, int pred){
  __shared__ float spid[Psz], spx[Psz], spy[Psz];
  __shared__ unsigned char garr[Psz];
  __shared__ int cnt[G2N], off[G2N+1];
  int p = blockIdx.x, q = threadIdx.x;
  if (pred){
    spid[q] = x[((size_t)(Ssz-1)*Psz + q)*3 + 0];
    spx[q]  = g_o[(q*Bsz + 0)*OUTN + 0];
    spy[q]  = g_o[(q*Bsz + 0)*OUTN + 1];
  } else {
    const float* xb = x + (size_t)(t*Psz)*3;
    spid[q] = xb[q*3+0]; spx[q] = xb[q*3+1]; spy[q] = xb[q*3+2];
  }
  __syncthreads();
  const float Rx = 0.2f, Ry = 0.2f, CELLF = 0.1f;
  float lx = spx[p]-Rx, rxb = spx[p]+Rx, by = spy[p]-Ry, ty = spy[p]+Ry;
  float ox = spx[q], oy = spy[q];
  bool inb   = (ox < rxb) && (ox >= lx) && (oy < ty) && (oy >= by);
  bool valid = (spid[p] != 0.f) && (spid[q] != 0.f) && (spid[p] != spid[q]);
  int cx = (int)floorf((ox - lx)/CELLF);
  int cy = (int)floorf((oy - by)/CELLF);
  int idx = cx + cy*4; idx = idx < 0 ? 0 : (idx > 15 ? 15 : idx);
  garr[q] = (inb && valid) ? (unsigned char)idx : (unsigned char)255;
  __syncthreads();
  if (q < G2N){
    int c = 0;
    for (int o = 0; o < Psz; o++) if (garr[o] == (unsigned char)q) c++;
    cnt[q] = c;
  }
  __syncthreads();
  if (q == 0){
    int s = 0; unsigned int act = 0;
    for (int g = 0; g < G2N; g++){ off[g] = s; if (cnt[g]) act |= (1u<<g); s += cnt[g]; }
    off[G2N] = s;
    g_active[p] = act;
    for (int g = 0; g <= G2N; g++) g_off[p*(G2N+1)+g] = off[g];
  }
  __syncthreads();
  if (q < G2N){
    int w = off[q];
    for (int o = 0; o < Psz; o++)
      if (garr[o] == (unsigned char)q) g_list[p*Psz + (w++)] = (unsigned char)o;
  }
}

// ---------------- fused hsum-build + soc GEMM + e, writes z = [e|a] ----------------
// Block = (b, 64-p tile). c[:,b,:] cached in smem; per active cell g the 64x128
// hsum tile is built in smem (EXACT R0 dual-accumulator even/odd order), then
// GEMM'd vs W_soc slice (k ascending within cell, cells ascending == R0 order).
#define PT     64
#define HS_STR 132
#define WS_STR 132
__global__ void __launch_bounds__(256, 1) k_fused(
    const float* __restrict__ x,
    const float* __restrict__ Wsoc,
    const float* __restrict__ bsoc,
    const float* __restrict__ Win,
    const float* __restrict__ bin,
    int t, int pred){
  extern __shared__ float dyn[];
  float* cs = dyn;                       // 256*128 = 131072 B
  float* hs = dyn + Psz*HIDN;            // 64*132
  float* ws = hs + PT*HS_STR;            // 2*16*132
  __shared__ unsigned char ls[PT*Psz];
  __shared__ int offs[PT*(G2N+1)];
  __shared__ int gl[G2N];
  __shared__ int s_ng;

  int b = blockIdx.x, pbase = blockIdx.y*PT;
  int tid = threadIdx.x;
  float4* cs4 = (float4*)cs;

  // load c[:,b,:] (all 256 p rows for this b)
  for (int i = tid; i < Psz*HIDN/4; i += 256){
    int o = i>>5, q = i&31;
    cs4[i] = *(const float4*)(g_c + ((size_t)o*Bsz + b)*HIDN + q*4);
  }
  // neighbor lists + offsets for this p-tile (contiguous copy)
  for (int i = tid; i < PT*Psz/16; i += 256)
    ((uint4*)ls)[i] = ((const uint4*)(g_list + (size_t)pbase*Psz))[i];
  for (int i = tid; i < PT*(G2N+1); i += 256)
    offs[i] = g_off[pbase*(G2N+1) + i];
  if (tid == 0){
    unsigned int u = 0;
    for (int pp = 0; pp < PT; pp++) u |= g_active[pbase+pp];
    int n = 0;
    for (int g = 0; g < G2N; g++) if ((u>>g)&1u) gl[n++] = g;
    s_ng = n;
  }
  __syncthreads();
  int ng = s_ng;

  int tx = tid & 31, ty = tid >> 5;     // warp = ty
  int n0 = tx*4, m0 = ty*8;
  float acc[8][4];
  #pragma unroll
  for (int i = 0; i < 8; i++){
    #pragma unroll
    for (int j = 0; j < 4; j++) acc[i][j] = 0.f;
  }

  if (ng > 0){
    // W tile loader: each thread owns 2 float4 (n-row, k-quad)
    int idx0 = tid, idx1 = tid + 256;
    int wn0 = idx0 >> 2, wk0 = (idx0 & 3)*4;
    int wn1 = idx1 >> 2, wk1 = (idx1 & 3)*4;
    float4 pv0, pv1;
    {
      int g = gl[0];
      pv0 = *(const float4*)(Wsoc + (size_t)wn0*2048 + g*128 + 0 + wk0);
      pv1 = *(const float4*)(Wsoc + (size_t)wn1*2048 + g*128 + 0 + wk1);
    }
    int buf = 0;
    for (int gi = 0; gi < ng; gi++){
      int g = gl[gi];
      // ---- build hsum tile [64 p][128 f] in smem ----
      // EXACT R0 summation order: dual accumulator, even list idx -> a0,
      // odd -> a1, tail -> a0, result a0 + a1 (per scalar component).
      #pragma unroll
      for (int i2 = 0; i2 < 8; i2++){
        int pl = ty*8 + i2;
        int s = offs[pl*(G2N+1)+g], e = offs[pl*(G2N+1)+g+1];
        float4 a0 = make_float4(0.f,0.f,0.f,0.f);
        float4 a1 = make_float4(0.f,0.f,0.f,0.f);
        int j = s;
        for (; j+1 < e; j += 2){
          float4 v0 = cs4[(int)ls[pl*Psz + j]*32 + tx];
          float4 v1 = cs4[(int)ls[pl*Psz + j+1]*32 + tx];
          a0.x += v0.x; a0.y += v0.y; a0.z += v0.z; a0.w += v0.w;
          a1.x += v1.x; a1.y += v1.y; a1.z += v1.z; a1.w += v1.w;
        }
        if (j < e){
          float4 v0 = cs4[(int)ls[pl*Psz + j]*32 + tx];
          a0.x += v0.x; a0.y += v0.y; a0.z += v0.z; a0.w += v0.w;
        }
        float4 r;
        r.x = a0.x + a1.x; r.y = a0.y + a1.y;
        r.z = a0.z + a1.z; r.w = a0.w + a1.w;
        *(float4*)(hs + pl*HS_STR + tx*4) = r;
      }
      __syncthreads();                      // hs ready
      // ---- GEMM over this g's K=128, kc chunks of 16, ping-pong W tiles ----
      for (int kc = 0; kc < 8; kc++){
        float* wb = ws + buf*16*WS_STR;
        // stage prefetched W into smem
        wb[(wk0+0)*WS_STR + wn0] = pv0.x;
        wb[(wk0+1)*WS_STR + wn0] = pv0.y;
        wb[(wk0+2)*WS_STR + wn0] = pv0.z;
        wb[(wk0+3)*WS_STR + wn0] = pv0.w;
        wb[(wk1+0)*WS_STR + wn1] = pv1.x;
        wb[(wk1+1)*WS_STR + wn1] = pv1.y;
        wb[(wk1+2)*WS_STR + wn1] = pv1.z;
        wb[(wk1+3)*WS_STR + wn1] = pv1.w;
        __syncthreads();                    // wb visible
        // prefetch next (kc+1) or next g's kc=0
        int nkc = kc + 1, ngi = gi;
        if (nkc == 8){ nkc = 0; ngi = gi + 1; }
        if (ngi < ng){
          int gg = gl[ngi];
          pv0 = *(const float4*)(Wsoc + (size_t)wn0*2048 + gg*128 + nkc*16 + wk0);
          pv1 = *(const float4*)(Wsoc + (size_t)wn1*2048 + gg*128 + nkc*16 + wk1);
        }
        // compute 16 k's (k ascending == R0 order)
        #pragma unroll
        for (int kq = 0; kq < 4; kq++){
          float4 hv[8];
          #pragma unroll
          for (int i = 0; i < 8; i++)
            hv[i] = *(const float4*)(hs + (m0+i)*HS_STR + kc*16 + kq*4);
          #pragma unroll
          for (int kk = 0; kk < 4; kk++){
            float4 w = *(const float4*)(wb + (kq*4+kk)*WS_STR + n0);
            #pragma unroll
            for (int i = 0; i < 8; i++){
              float h = ((const float*)&hv[i])[kk];
              acc[i][0] += h*w.x; acc[i][1] += h*w.y;
              acc[i][2] += h*w.z; acc[i][3] += h*w.w;
            }
          }
        }
        buf ^= 1;
      }
      __syncthreads();                      // protect hs before next build
    }
  }

  // ---- epilogue: a = relu(acc + b_soc) -> z[:,64:192] ----
  float4 bv = *(const float4*)(bsoc + n0);
  #pragma unroll
  for (int i = 0; i < 8; i++){
    int r = (pbase + m0 + i)*Bsz + b;
    float4 o;
    o.x = fmaxf(acc[i][0] + bv.x, 0.f);
    o.y = fmaxf(acc[i][1] + bv.y, 0.f);
    o.z = fmaxf(acc[i][2] + bv.z, 0.f);
    o.w = fmaxf(acc[i][3] + bv.w, 0.f);
    *(float4*)(g_z + (size_t)r*ZC + MIDN + n0) = o;
  }
  // ---- e = relu(pos @ Win^T + bin) -> z[:,0:64] ----
  for (int i2 = tid; i2 < PT*MIDN; i2 += 256){
    int mm = i2 >> 6, j = i2 & 63;
    int p = pbase + mm;
    int r = p*Bsz + b;
    float px, py;
    if (pred){ px = g_o[r*OUTN+0]; py = g_o[r*OUTN+1]; }
    else {
      const float* xr = x + (size_t)(((b*Ssz)+t)*Psz + p)*3;
      px = xr[1]; py = xr[2];
    }
    float v = px*Win[j*2+0] + py*Win[j*2+1] + bin[j];
    g_z[(size_t)r*ZC + j] = v > 0.f ? v : 0.f;
  }
}

// ---------------- LSTM gates (i,g,o only; f is dead) -> c, h ----------------
__global__ void k_lstm(const float* __restrict__ Wih,
                       const float* __restrict__ bih,
                       const float* __restrict__ bhh){
  __shared__ float Zs[16][68];
  __shared__ float Wg3[3][16][36];
  int mt = blockIdx.x, jt = blockIdx.y;
  int r0 = mt*64, j0 = jt*32;
  int tI = threadIdx.x;
  int tx = tI & 31, ty = tI >> 5;
  int m0 = ty*8;
  float ai[8], ag[8], ao[8];
  #pragma unroll
  for (int i = 0; i < 8; i++){ ai[i]=0.f; ag[i]=0.f; ao[i]=0.f; }
  int lm = tI >> 2, lk = (tI & 3)*4;
  for (int kc = 0; kc < 12; kc++){
    int kb = kc*16;
    float4 zv = *(const float4*)(g_z + (size_t)(r0+lm)*ZC + kb + lk);
    float4 wv[2]; int wg[2], wj[2], wk[2]; bool wval[2];
    #pragma unroll
    for (int i = 0; i < 2; i++){
      int idx = tI + i*256; wval[i] = idx < 384;
      wg[i]=0; wj[i]=0; wk[i]=0;
      if (wval[i]){
        wg[i] = idx/128; int rs = idx%128; wj[i] = rs>>2; wk[i] = (rs&3)*4;
        int baser = (wg[i]==0?0:(wg[i]==1?256:384)) + j0 + wj[i];
        wv[i] = *(const float4*)(Wih + (size_t)baser*ZC + kb + wk[i]);
      }
    }
    __syncthreads();
    Zs[lk+0][lm]=zv.x; Zs[lk+1][lm]=zv.y; Zs[lk+2][lm]=zv.z; Zs[lk+3][lm]=zv.w;
    #pragma unroll
    for (int i = 0; i < 2; i++){
      if (wval[i]){
        Wg3[wg[i]][wk[i]+0][wj[i]]=wv[i].x; Wg3[wg[i]][wk[i]+1][wj[i]]=wv[i].y;
        Wg3[wg[i]][wk[i]+2][wj[i]]=wv[i].z; Wg3[wg[i]][wk[i]+3][wj[i]]=wv[i].w;
      }
    }
    __syncthreads();
    #pragma unroll
    for (int kk = 0; kk < 16; kk++){
      float4 z0 = *(const float4*)(&Zs[kk][m0]);
      float4 z1 = *(const float4*)(&Zs[kk][m0+4]);
      float zz[8] = {z0.x,z0.y,z0.z,z0.w,z1.x,z1.y,z1.z,z1.w};
      float wi = Wg3[0][kk][tx], wgg = Wg3[1][kk][tx], wo = Wg3[2][kk][tx];
      #pragma unroll
      for (int i = 0; i < 8; i++){
        ai[i] += zz[i]*wi; ag[i] += zz[i]*wgg; ao[i] += zz[i]*wo;
      }
    }
    __syncthreads();
  }
  int j = j0 + tx;
  float bi_ = bih[j]       + bhh[j];
  float bg_ = bih[256 + j] + bhh[256 + j];
  float bo_ = bih[384 + j] + bhh[384 + j];
  #pragma unroll
  for (int i = 0; i < 8; i++){
    int r = r0 + m0 + i;
    float ci = sigf(ai[i]+bi_)*tanhf(ag[i]+bg_);
    float hh = sigf(ao[i]+bo_)*tanhf(ci);
    g_c[(size_t)r*HIDN + j] = ci;
    g_h[(size_t)r*HIDN + j] = hh;
  }
}

// ---------------- output head o = h @ Wout^T + bout ----------------
__global__ void k_out(const float* __restrict__ Wout, const float* __restrict__ bout,
                      float* __restrict__ out, int pred, int kstep){
  int warp = threadIdx.x >> 5, lane = threadIdx.x & 31;
  int r = blockIdx.x*8 + warp;
  float hv[4];
  #pragma unroll
  for (int i = 0; i < 4; i++) hv[i] = g_h[(size_t)r*HIDN + lane + i*32];
  float res[5];
  #pragma unroll
  for (int c = 0; c < 5; c++){
    float s = 0.f;
    #pragma unroll
    for (int i = 0; i < 4; i++) s += hv[i]*__ldg(Wout + c*HIDN + lane + i*32);
    #pragma unroll
    for (int d = 16; d > 0; d >>= 1) s += __shfl_xor_sync(0xffffffffu, s, d);
    res[c] = s + bout[c];
  }
  if (lane == 0){
    int b = r & 31, p = r >> 5;
    #pragma unroll
    for (int c = 0; c < 5; c++){
      g_o[r*OUTN + c] = res[c];
      if (pred)
        out[(size_t)XP_ELEMS + ((size_t)(b*PREDN + kstep)*Psz + p)*OUTN + c] = res[c];
    }
  }
}

// ---------------- write xp[b,k,p,:] = (pid, prev o.xy) ----------------
__global__ void k_xpwrite(const float* __restrict__ x, float* __restrict__ out, int kstep){
  int i = blockIdx.x*256 + threadIdx.x;   // i == r == p*32+b
  if (i >= RROWS) return;
  int b = i & 31, p = i >> 5;
  float pid = x[((size_t)(b*Ssz + Ssz-1)*Psz + p)*3 + 0];
  size_t base = ((size_t)(b*PREDN + kstep)*Psz + p)*3;
  out[base+0] = pid;
  out[base+1] = g_o[i*OUTN + 0];
  out[base+2] = g_o[i*OUTN + 1];
}

// ---------------- launch ----------------
extern "C" void kernel_launch(void* const* d_in, const int* in_sizes, int n_in,
                              void* d_out, int out_size){
  const float* x    = (const float*)d_in[0];
  const float* Win  = (const float*)d_in[1];
  const float* bin  = (const float*)d_in[2];
  const float* Wsoc = (const float*)d_in[3];
  const float* bsoc = (const float*)d_in[4];
  const float* bprev= (const float*)d_in[5];
  const float* Wih  = (const float*)d_in[6];
  const float* bih  = (const float*)d_in[7];
  const float* bhh  = (const float*)d_in[8];
  const float* Wout = (const float*)d_in[9];
  const float* bout = (const float*)d_in[10];
  float* out = (float*)d_out;

  const int DYN = (Psz*HIDN + PT*HS_STR + 2*16*WS_STR)*(int)sizeof(float);
  cudaFuncSetAttribute(k_fused, cudaFuncAttributeMaxDynamicSharedMemorySize, DYN);

  k_init<<<(RROWS*HIDN + 255)/256, 256>>>(bprev);
  for (int t = 0; t < OBSN; t++){
    k_mask<<<Psz, Psz>>>(x, t, 0);
    k_fused<<<dim3(Bsz, Psz/PT), 256, DYN>>>(x, Wsoc, bsoc, Win, bin, t, 0);
    k_lstm<<<dim3(RROWS/64, 4), 256>>>(Wih, bih, bhh);
    k_out<<<RROWS/8, 256>>>(Wout, bout, out, 0, 0);
  }
  for (int k = 0; k < PREDN; k++){
    k_xpwrite<<<RROWS/256, 256>>>(x, out, k);
    k_mask<<<Psz, Psz>>>(x, 0, 1);
    k_fused<<<dim3(Bsz, Psz/PT), 256, DYN>>>(x, Wsoc, bsoc, Win, bin, 0, 1);
    k_lstm<<<dim3(RROWS/64, 4), 256>>>(Wih, bih, bhh);
    k_out<<<RROWS/8, 256>>>(Wout, bout, out, 1, k);
  }
}